// round 1
// baseline (speedup 1.0000x reference)
#include <cuda_runtime.h>
#include <math.h>

#define BB 8
#define TT 2048
#define HH 1024
#define DD 64
#define NTOK (BB*TT)   // 16384

// scratch for projected q,k,v (allocation-free rule: __device__ globals)
__device__ float g_q[NTOK*DD];
__device__ float g_k[NTOK*DD];
__device__ float g_v[NTOK*DD];

// ---------------------------------------------------------------------------
// Projection GEMM: y[m][d] = sum_h x[m][h] * W[h][d]
// M=16384, N=64, K=1024. Block tile 128x64, k-tile 32. 256 threads,
// 8x4 register tile per thread. blockIdx.y selects {q,k,v}.
// ---------------------------------------------------------------------------
__global__ __launch_bounds__(256) void proj_kernel(
    const float* __restrict__ x,
    const float* __restrict__ Wk,
    const float* __restrict__ Wq,
    const float* __restrict__ Wv)
{
    const float* W;
    float* out;
    if (blockIdx.y == 0)      { W = Wq; out = g_q; }
    else if (blockIdx.y == 1) { W = Wk; out = g_k; }
    else                      { W = Wv; out = g_v; }

    __shared__ float xs[128][36];   // pad to 36 (16B-aligned rows)
    __shared__ float ws[32][64];

    const int t   = threadIdx.x;
    const int ty  = t >> 4;         // 0..15 -> rows ty*8..ty*8+7
    const int tx  = t & 15;         // 0..15 -> cols tx*4..tx*4+3
    const int row0 = blockIdx.x * 128;

    float acc[8][4];
    #pragma unroll
    for (int i = 0; i < 8; i++)
        #pragma unroll
        for (int j = 0; j < 4; j++) acc[i][j] = 0.f;

    for (int k0 = 0; k0 < HH; k0 += 32) {
        // load x tile: 128x32 = 1024 float4, 4 per thread
        #pragma unroll
        for (int i = 0; i < 4; i++) {
            int f4 = t + i * 256;
            int r = f4 >> 3, c4 = f4 & 7;
            float4 v = *(const float4*)&x[(size_t)(row0 + r) * HH + k0 + c4 * 4];
            *(float4*)&xs[r][c4 * 4] = v;
        }
        // load W tile: 32x64 = 512 float4, 2 per thread
        #pragma unroll
        for (int i = 0; i < 2; i++) {
            int f4 = t + i * 256;
            int r = f4 >> 4, c4 = f4 & 15;
            *(float4*)&ws[r][c4 * 4] = *(const float4*)&W[(size_t)(k0 + r) * DD + c4 * 4];
        }
        __syncthreads();

        #pragma unroll
        for (int kk = 0; kk < 32; kk++) {
            float a[8];
            #pragma unroll
            for (int i = 0; i < 8; i++) a[i] = xs[ty * 8 + i][kk];
            float4 b4 = *(const float4*)&ws[kk][tx * 4];
            float b[4] = {b4.x, b4.y, b4.z, b4.w};
            #pragma unroll
            for (int i = 0; i < 8; i++)
                #pragma unroll
                for (int j = 0; j < 4; j++)
                    acc[i][j] = fmaf(a[i], b[j], acc[i][j]);
        }
        __syncthreads();
    }

    #pragma unroll
    for (int i = 0; i < 8; i++) {
        float4 v = make_float4(acc[i][0], acc[i][1], acc[i][2], acc[i][3]);
        *(float4*)&out[(size_t)(row0 + ty * 8 + i) * DD + tx * 4] = v;
    }
}

// ---------------------------------------------------------------------------
// Flash attention (fp32, causal). Q-tile = 64 rows. Each block handles the
// balanced q-tile pair {p, 31-p} for one batch: exactly 33 k-tiles of work.
// 256 threads = 64 rows x 4 groups. S phase: thread(row,cg) covers columns
// c = j*4+cg. PV phase: thread(row,cg) covers d = d4*16 + cg*4 + e.
// Smem rows padded to 68 floats -> lane groups hit distinct banks.
// ---------------------------------------------------------------------------
#define PAD 68
#define ATTN_SMEM (4 * 64 * PAD * 4)

__global__ __launch_bounds__(256) void attn_kernel(float* __restrict__ out)
{
    extern __shared__ float sm[];
    float* qs = sm;
    float* ks = sm + 64 * PAD;
    float* vs = sm + 2 * 64 * PAD;
    float* ps = sm + 3 * 64 * PAD;

    const int t   = threadIdx.x;
    const int row = t >> 2;
    const int cg  = t & 3;
    const int b   = blockIdx.x >> 4;
    const int p   = blockIdx.x & 15;

    for (int half = 0; half < 2; half++) {
        const int qt = (half == 0) ? p : (31 - p);
        const float* qbase = g_q + ((size_t)b * TT + qt * 64) * DD;

        // load Q tile (64x64 = 1024 float4, 4 per thread)
        #pragma unroll
        for (int i = 0; i < 4; i++) {
            int f4 = t + i * 256;
            int r = f4 >> 4, c4 = f4 & 15;
            *(float4*)&qs[r * PAD + c4 * 4] =
                *(const float4*)&qbase[r * DD + c4 * 4];
        }

        float m = -INFINITY, l = 0.f;
        float o[16];
        #pragma unroll
        for (int i = 0; i < 16; i++) o[i] = 0.f;

        for (int kt = 0; kt <= qt; kt++) {
            __syncthreads();   // prev iter's smem reads done; qs visible on iter 0

            const float* kbase = g_k + ((size_t)b * TT + kt * 64) * DD;
            const float* vbase = g_v + ((size_t)b * TT + kt * 64) * DD;
            #pragma unroll
            for (int i = 0; i < 4; i++) {
                int f4 = t + i * 256;
                int r = f4 >> 4, c4 = f4 & 15;
                *(float4*)&ks[r * PAD + c4 * 4] =
                    *(const float4*)&kbase[r * DD + c4 * 4];
                *(float4*)&vs[r * PAD + c4 * 4] =
                    *(const float4*)&vbase[r * DD + c4 * 4];
            }
            __syncthreads();

            // S = Q K^T * 0.125  (16 columns per thread: c = j*4+cg)
            float s[16];
            #pragma unroll
            for (int j = 0; j < 16; j++) s[j] = 0.f;
            #pragma unroll 4
            for (int d4 = 0; d4 < 16; d4++) {
                float4 q4 = *(const float4*)&qs[row * PAD + d4 * 4];
                #pragma unroll
                for (int j = 0; j < 16; j++) {
                    int c = j * 4 + cg;
                    float4 k4 = *(const float4*)&ks[c * PAD + d4 * 4];
                    s[j] = fmaf(q4.x, k4.x, s[j]);
                    s[j] = fmaf(q4.y, k4.y, s[j]);
                    s[j] = fmaf(q4.z, k4.z, s[j]);
                    s[j] = fmaf(q4.w, k4.w, s[j]);
                }
            }

            const bool diag = (kt == qt);
            float mx = -INFINITY;
            #pragma unroll
            for (int j = 0; j < 16; j++) {
                s[j] *= 0.125f;
                if (diag && (j * 4 + cg) > row) s[j] = -INFINITY;
                mx = fmaxf(mx, s[j]);
            }
            // row max across the 4-thread quad
            mx = fmaxf(mx, __shfl_xor_sync(0xffffffffu, mx, 1));
            mx = fmaxf(mx, __shfl_xor_sync(0xffffffffu, mx, 2));

            float mnew = fmaxf(m, mx);
            float corr = __expf(m - mnew);  // 0 on first tile (m = -inf)

            float lsum = 0.f;
            #pragma unroll
            for (int j = 0; j < 16; j++) {
                float pj = __expf(s[j] - mnew);
                ps[row * PAD + j * 4 + cg] = pj;
                lsum += pj;
            }
            lsum += __shfl_xor_sync(0xffffffffu, lsum, 1);
            lsum += __shfl_xor_sync(0xffffffffu, lsum, 2);

            l = l * corr + lsum;
            m = mnew;
            #pragma unroll
            for (int i = 0; i < 16; i++) o[i] *= corr;

            __syncthreads();   // ps visible

            // O += P @ V  (thread covers d = d4*16 + cg*4 + e)
            #pragma unroll 8
            for (int c = 0; c < 64; c++) {
                float pv = ps[row * PAD + c];
                #pragma unroll
                for (int d4 = 0; d4 < 4; d4++) {
                    float4 v4 = *(const float4*)&vs[c * PAD + d4 * 16 + cg * 4];
                    o[d4 * 4 + 0] = fmaf(pv, v4.x, o[d4 * 4 + 0]);
                    o[d4 * 4 + 1] = fmaf(pv, v4.y, o[d4 * 4 + 1]);
                    o[d4 * 4 + 2] = fmaf(pv, v4.z, o[d4 * 4 + 2]);
                    o[d4 * 4 + 3] = fmaf(pv, v4.w, o[d4 * 4 + 3]);
                }
            }
        }

        const float inv = 1.f / l;
        float* obase = out + ((size_t)b * TT + qt * 64 + row) * DD;
        #pragma unroll
        for (int d4 = 0; d4 < 4; d4++) {
            float4 w = make_float4(o[d4 * 4 + 0] * inv, o[d4 * 4 + 1] * inv,
                                   o[d4 * 4 + 2] * inv, o[d4 * 4 + 3] * inv);
            *(float4*)&obase[d4 * 16 + cg * 4] = w;
        }
        __syncthreads();   // before next half reloads qs
    }
}

// ---------------------------------------------------------------------------
extern "C" void kernel_launch(void* const* d_in, const int* in_sizes, int n_in,
                              void* d_out, int out_size)
{
    const float* x  = (const float*)d_in[0];
    const float* Wk = (const float*)d_in[1];
    const float* Wq = (const float*)d_in[2];
    const float* Wv = (const float*)d_in[3];
    float* out = (float*)d_out;

    cudaFuncSetAttribute(attn_kernel,
                         cudaFuncAttributeMaxDynamicSharedMemorySize, ATTN_SMEM);

    dim3 pgrid(NTOK / 128, 3);
    proj_kernel<<<pgrid, 256>>>(x, Wk, Wq, Wv);

    attn_kernel<<<BB * 16, 256, ATTN_SMEM>>>(out);
}

// round 2
// speedup vs baseline: 2.8029x; 2.8029x over previous
#include <cuda_runtime.h>
#include <math.h>
#include <stdint.h>

#define BB 8
#define TT 2048
#define HH 1024
#define DD 64
#define NTOK (BB*TT)   // 16384

// scratch for projected q,k,v
__device__ float g_q[NTOK*DD];
__device__ float g_k[NTOK*DD];
__device__ float g_v[NTOK*DD];

// ---------------------------------------------------------------------------
// helpers
// ---------------------------------------------------------------------------
__device__ __forceinline__ uint32_t f2tf(float f) {
    uint32_t r; asm("cvt.rna.tf32.f32 %0, %1;" : "=r"(r) : "f"(f)); return r;
}

__device__ __forceinline__ void mma8(float c[4],
    uint32_t a0, uint32_t a1, uint32_t a2, uint32_t a3,
    uint32_t b0, uint32_t b1)
{
    asm volatile(
        "mma.sync.aligned.m16n8k8.row.col.f32.tf32.tf32.f32 "
        "{%0,%1,%2,%3}, {%4,%5,%6,%7}, {%8,%9}, {%0,%1,%2,%3};"
        : "+f"(c[0]), "+f"(c[1]), "+f"(c[2]), "+f"(c[3])
        : "r"(a0), "r"(a1), "r"(a2), "r"(a3), "r"(b0), "r"(b1));
}

// column permutation: puts logical cols (c, c+4) adjacent -> 64-bit frag loads
__device__ __forceinline__ int perm8(int c) {
    return (c & ~7) | ((c & 3) << 1) | ((c >> 2) & 1);
}

// 64-col arrays (attn): scalar store index / uint2 frag load, XOR swizzle
__device__ __forceinline__ int swz64(int r, int c /*permuted col*/) {
    int c2 = c >> 1;
    return r * 64 + (((c2 ^ ((r & 3) << 2)) << 1) | (c & 1));
}
__device__ __forceinline__ uint2 ld64(const uint32_t* a, int r, int c2) {
    return ((const uint2*)a)[r * 32 + (c2 ^ ((r & 3) << 2))];
}

// 32-col arrays (proj)
__device__ __forceinline__ int swz32(int r, int c) {
    int c2 = c >> 1;
    return r * 32 + (((c2 ^ ((r & 3) << 2)) << 1) | (c & 1));
}
__device__ __forceinline__ uint2 ld32(const uint32_t* a, int r, int c2) {
    return ((const uint2*)a)[r * 16 + (c2 ^ ((r & 3) << 2))];
}

// ---------------------------------------------------------------------------
// Fused projection: y = x @ [Wq|Wk|Wv], M=16384, N=192, K=1024, tf32 mma.
// Block tile M=128, N=192, k-chunk 32. 512 threads = 16 warps (4m x 4n),
// warp tile 32x48 = 2 m-tiles x 6 n-tiles.
// ---------------------------------------------------------------------------
__global__ __launch_bounds__(512) void proj_kernel(
    const float* __restrict__ x,
    const float* __restrict__ Wk,
    const float* __restrict__ Wq,
    const float* __restrict__ Wv)
{
    __shared__ uint32_t xs[128 * 32];   // x tile, tf32, swizzled
    __shared__ uint32_t wt[192 * 32];   // W^T tile [n][k], tf32, swizzled

    const int t    = threadIdx.x;
    const int lane = t & 31;
    const int warp = t >> 5;
    const int g    = lane >> 2;
    const int tig  = lane & 3;
    const int warpM = warp >> 2;   // 0..3
    const int warpN = warp & 3;    // 0..3
    const int row0 = blockIdx.x * 128;

    float acc[2][6][4];
    #pragma unroll
    for (int a = 0; a < 2; a++)
        #pragma unroll
        for (int j = 0; j < 6; j++)
            #pragma unroll
            for (int e = 0; e < 4; e++) acc[a][j][e] = 0.f;

    for (int k0 = 0; k0 < HH; k0 += 32) {
        __syncthreads();
        // x tile: 128x32 floats = 1024 float4, 2 per thread
        #pragma unroll
        for (int i = 0; i < 2; i++) {
            int f4 = t + i * 512;
            int r = f4 >> 3, c0 = (f4 & 7) * 4;
            float4 v = *(const float4*)&x[(size_t)(row0 + r) * HH + k0 + c0];
            xs[swz32(r, perm8(c0 + 0))] = f2tf(v.x);
            xs[swz32(r, perm8(c0 + 1))] = f2tf(v.y);
            xs[swz32(r, perm8(c0 + 2))] = f2tf(v.z);
            xs[swz32(r, perm8(c0 + 3))] = f2tf(v.w);
        }
        // W^T tile: 768 tasks, each = two float4 rows (k, k+4) -> 4 uint2
        #pragma unroll
        for (int i = 0; i < 2; i++) {
            int tau = t + i * 512;
            if (tau < 768) {
                int kp = tau & 15, n4 = tau >> 4;
                int k  = ((kp >> 2) << 3) | (kp & 3);   // 0,1,2,3,8,9,...27
                int n0 = n4 * 4;                         // 0..188
                const float* W = (n0 < 64) ? Wq : (n0 < 128) ? Wk : Wv;
                int ncol = n0 & 63;
                float4 lo = *(const float4*)&W[(size_t)(k0 + k)     * DD + ncol];
                float4 hi = *(const float4*)&W[(size_t)(k0 + k + 4) * DD + ncol];
                int col2 = ((k & ~7) >> 1) | (k & 3);
                uint2* w2 = (uint2*)wt;
                w2[(n0 + 0) * 16 + (col2 ^ 0)]  = make_uint2(f2tf(lo.x), f2tf(hi.x));
                w2[(n0 + 1) * 16 + (col2 ^ 4)]  = make_uint2(f2tf(lo.y), f2tf(hi.y));
                w2[(n0 + 2) * 16 + (col2 ^ 8)]  = make_uint2(f2tf(lo.z), f2tf(hi.z));
                w2[(n0 + 3) * 16 + (col2 ^ 12)] = make_uint2(f2tf(lo.w), f2tf(hi.w));
            }
        }
        __syncthreads();

        #pragma unroll
        for (int ks = 0; ks < 4; ks++) {
            int c2 = ks * 4 + tig;
            int rA = warpM * 32 + g;
            uint2 A02_0 = ld32(xs, rA,      c2);
            uint2 A13_0 = ld32(xs, rA + 8,  c2);
            uint2 A02_1 = ld32(xs, rA + 16, c2);
            uint2 A13_1 = ld32(xs, rA + 24, c2);
            #pragma unroll
            for (int j = 0; j < 6; j++) {
                int n = warpN * 48 + j * 8 + g;
                uint2 B = ld32(wt, n, c2);
                mma8(acc[0][j], A02_0.x, A13_0.x, A02_0.y, A13_0.y, B.x, B.y);
                mma8(acc[1][j], A02_1.x, A13_1.x, A02_1.y, A13_1.y, B.x, B.y);
            }
        }
    }

    #pragma unroll
    for (int mt = 0; mt < 2; mt++) {
        int r = row0 + warpM * 32 + mt * 16 + g;
        #pragma unroll
        for (int j = 0; j < 6; j++) {
            int nb = warpN * 48 + j * 8;
            float* o = (nb < 64) ? g_q : (nb < 128) ? g_k : g_v;
            int c = (nb & 63) + 2 * tig;
            *(float2*)&o[(size_t)r       * DD + c] = make_float2(acc[mt][j][0], acc[mt][j][1]);
            *(float2*)&o[(size_t)(r + 8) * DD + c] = make_float2(acc[mt][j][2], acc[mt][j][3]);
        }
    }
}

// ---------------------------------------------------------------------------
// Flash attention, tf32 mma. 128 threads = 4 warps, each warp owns 16 q-rows.
// Balanced pair {p, 31-p} of 64-row q-tiles per block: 33 k-tiles each.
// smem: qs, ks (row-major tf32), vt (V^T), ps (P) — all swizzled 64x64.
// ---------------------------------------------------------------------------
#define ATTN_SMEM 65536

__global__ __launch_bounds__(128) void attn_kernel(float* __restrict__ out)
{
    extern __shared__ uint32_t sm[];
    uint32_t* qs = sm;
    uint32_t* ks = sm + 4096;
    uint32_t* vt = sm + 8192;
    uint32_t* ps = sm + 12288;

    const int t    = threadIdx.x;
    const int lane = t & 31;
    const int warp = t >> 5;
    const int g    = lane >> 2;
    const int tig  = lane & 3;
    const int wr   = warp * 16;
    const int b    = blockIdx.x >> 4;
    const int p    = blockIdx.x & 15;

    for (int half = 0; half < 2; half++) {
        const int qt = half ? (31 - p) : p;
        const float* qbase = g_q + ((size_t)(b * TT + qt * 64)) * DD;

        // load Q tile (tf32, permuted+swizzled): 1024 float4, 8 per thread
        #pragma unroll
        for (int i = 0; i < 8; i++) {
            int f4 = t + i * 128;
            int r = f4 >> 4, c0 = (f4 & 15) * 4;
            float4 v = *(const float4*)&qbase[r * DD + c0];
            qs[swz64(r, perm8(c0 + 0))] = f2tf(v.x);
            qs[swz64(r, perm8(c0 + 1))] = f2tf(v.y);
            qs[swz64(r, perm8(c0 + 2))] = f2tf(v.z);
            qs[swz64(r, perm8(c0 + 3))] = f2tf(v.w);
        }

        float m0 = -INFINITY, m1 = -INFINITY, l0 = 0.f, l1 = 0.f;
        float o[8][4];
        #pragma unroll
        for (int nt = 0; nt < 8; nt++)
            #pragma unroll
            for (int e = 0; e < 4; e++) o[nt][e] = 0.f;

        for (int kt = 0; kt <= qt; kt++) {
            __syncthreads();
            const float* kbase = g_k + ((size_t)(b * TT + kt * 64)) * DD;
            const float* vbase = g_v + ((size_t)(b * TT + kt * 64)) * DD;

            // K tile
            #pragma unroll
            for (int i = 0; i < 8; i++) {
                int f4 = t + i * 128;
                int r = f4 >> 4, c0 = (f4 & 15) * 4;
                float4 v = *(const float4*)&kbase[r * DD + c0];
                ks[swz64(r, perm8(c0 + 0))] = f2tf(v.x);
                ks[swz64(r, perm8(c0 + 1))] = f2tf(v.y);
                ks[swz64(r, perm8(c0 + 2))] = f2tf(v.z);
                ks[swz64(r, perm8(c0 + 3))] = f2tf(v.w);
            }
            // V tile -> V^T (pair rows c, c+4 packed into uint2)
            #pragma unroll
            for (int i = 0; i < 4; i++) {
                int tau = t + i * 128;
                int pc = tau & 31, j = tau >> 5;
                int c = ((pc >> 2) << 3) | (pc & 3);
                const float* vb = vbase + c * DD + j * 4;
                float4 lo = *(const float4*)vb;
                float4 hi = *(const float4*)(vb + 4 * DD);
                int col2 = ((c & ~7) >> 1) | (c & 3);
                uint2* v2 = (uint2*)vt;
                v2[(4 * j + 0) * 32 + (col2 ^ 0)]  = make_uint2(f2tf(lo.x), f2tf(hi.x));
                v2[(4 * j + 1) * 32 + (col2 ^ 4)]  = make_uint2(f2tf(lo.y), f2tf(hi.y));
                v2[(4 * j + 2) * 32 + (col2 ^ 8)]  = make_uint2(f2tf(lo.z), f2tf(hi.z));
                v2[(4 * j + 3) * 32 + (col2 ^ 12)] = make_uint2(f2tf(lo.w), f2tf(hi.w));
            }
            __syncthreads();

            // ---- S = Q K^T ----
            float s[8][4];
            #pragma unroll
            for (int nt = 0; nt < 8; nt++)
                #pragma unroll
                for (int e = 0; e < 4; e++) s[nt][e] = 0.f;

            #pragma unroll
            for (int ksx = 0; ksx < 8; ksx++) {
                int c2 = ksx * 4 + tig;
                uint2 A02 = ld64(qs, wr + g,     c2);
                uint2 A13 = ld64(qs, wr + g + 8, c2);
                #pragma unroll
                for (int nt = 0; nt < 8; nt++) {
                    uint2 B = ld64(ks, nt * 8 + g, c2);
                    mma8(s[nt], A02.x, A13.x, A02.y, A13.y, B.x, B.y);
                }
            }

            // ---- softmax ----
            const bool diag = (kt == qt);
            const int r0 = wr + g, r1 = wr + g + 8;
            float mx0 = -INFINITY, mx1 = -INFINITY;
            #pragma unroll
            for (int nt = 0; nt < 8; nt++) {
                int c0 = nt * 8 + 2 * tig;
                s[nt][0] *= 0.125f; s[nt][1] *= 0.125f;
                s[nt][2] *= 0.125f; s[nt][3] *= 0.125f;
                if (diag) {
                    if (c0     > r0) s[nt][0] = -INFINITY;
                    if (c0 + 1 > r0) s[nt][1] = -INFINITY;
                    if (c0     > r1) s[nt][2] = -INFINITY;
                    if (c0 + 1 > r1) s[nt][3] = -INFINITY;
                }
                mx0 = fmaxf(mx0, fmaxf(s[nt][0], s[nt][1]));
                mx1 = fmaxf(mx1, fmaxf(s[nt][2], s[nt][3]));
            }
            mx0 = fmaxf(mx0, __shfl_xor_sync(0xffffffffu, mx0, 1));
            mx0 = fmaxf(mx0, __shfl_xor_sync(0xffffffffu, mx0, 2));
            mx1 = fmaxf(mx1, __shfl_xor_sync(0xffffffffu, mx1, 1));
            mx1 = fmaxf(mx1, __shfl_xor_sync(0xffffffffu, mx1, 2));

            float M0 = fmaxf(m0, mx0), M1 = fmaxf(m1, mx1);
            float corr0 = __expf(m0 - M0), corr1 = __expf(m1 - M1);

            float ls0 = 0.f, ls1 = 0.f;
            #pragma unroll
            for (int nt = 0; nt < 8; nt++) {
                int c0 = nt * 8 + 2 * tig;
                float p0 = __expf(s[nt][0] - M0);
                float p1 = __expf(s[nt][1] - M0);
                float p2 = __expf(s[nt][2] - M1);
                float p3 = __expf(s[nt][3] - M1);
                ls0 += p0 + p1; ls1 += p2 + p3;
                ps[swz64(r0, perm8(c0))]     = f2tf(p0);
                ps[swz64(r0, perm8(c0 + 1))] = f2tf(p1);
                ps[swz64(r1, perm8(c0))]     = f2tf(p2);
                ps[swz64(r1, perm8(c0 + 1))] = f2tf(p3);
            }
            ls0 += __shfl_xor_sync(0xffffffffu, ls0, 1);
            ls0 += __shfl_xor_sync(0xffffffffu, ls0, 2);
            ls1 += __shfl_xor_sync(0xffffffffu, ls1, 1);
            ls1 += __shfl_xor_sync(0xffffffffu, ls1, 2);

            l0 = l0 * corr0 + ls0; m0 = M0;
            l1 = l1 * corr1 + ls1; m1 = M1;
            #pragma unroll
            for (int nt = 0; nt < 8; nt++) {
                o[nt][0] *= corr0; o[nt][1] *= corr0;
                o[nt][2] *= corr1; o[nt][3] *= corr1;
            }
            __syncwarp();   // ps is warp-local (rows wr..wr+15)

            // ---- O += P V ----
            #pragma unroll
            for (int ksx = 0; ksx < 8; ksx++) {
                int c2 = ksx * 4 + tig;
                uint2 A02 = ld64(ps, wr + g,     c2);
                uint2 A13 = ld64(ps, wr + g + 8, c2);
                #pragma unroll
                for (int nt = 0; nt < 8; nt++) {
                    uint2 B = ld64(vt, nt * 8 + g, c2);
                    mma8(o[nt], A02.x, A13.x, A02.y, A13.y, B.x, B.y);
                }
            }
        }

        const float inv0 = 1.f / l0, inv1 = 1.f / l1;
        float* ob = out + ((size_t)(b * TT + qt * 64)) * DD;
        #pragma unroll
        for (int nt = 0; nt < 8; nt++) {
            int c = nt * 8 + 2 * tig;
            *(float2*)&ob[(wr + g)     * DD + c] =
                make_float2(o[nt][0] * inv0, o[nt][1] * inv0);
            *(float2*)&ob[(wr + g + 8) * DD + c] =
                make_float2(o[nt][2] * inv1, o[nt][3] * inv1);
        }
        __syncthreads();   // qs reload next half
    }
}

// ---------------------------------------------------------------------------
extern "C" void kernel_launch(void* const* d_in, const int* in_sizes, int n_in,
                              void* d_out, int out_size)
{
    const float* x  = (const float*)d_in[0];
    const float* Wk = (const float*)d_in[1];
    const float* Wq = (const float*)d_in[2];
    const float* Wv = (const float*)d_in[3];
    float* out = (float*)d_out;

    cudaFuncSetAttribute(attn_kernel,
                         cudaFuncAttributeMaxDynamicSharedMemorySize, ATTN_SMEM);

    proj_kernel<<<NTOK / 128, 512>>>(x, Wk, Wq, Wv);
    attn_kernel<<<BB * 16, 128, ATTN_SMEM>>>(out);
}